// round 11
// baseline (speedup 1.0000x reference)
#include <cuda_runtime.h>

// MatchAttention fused forward, fixed shape:
// B=2, H=W=64, N=4096, C=256, heads=8, Ch=32, r=3 -> K=49, scale=1, l1_norm.
#define HH   64
#define WW   64
#define CC   256
#define NHD  8
#define CH   32
#define RR   3
#define KWIN 49
#define NPIX (HH * WW)

// One warp = 4 heads of one pixel (8 lanes/head, 4 channels/lane).
// 12 groups of 4 slots + remainder, software-pipelined:
//   k-loads of group j+1 issue BEFORE group j's butterfly;
//   v-loads of group j issue right after its addresses, consumed at group end.
// 4-slot reduce: 3 butterfly rounds leave slot t's full distance on lanes
// {t, t+4}; 4 broadcast shfls put all 4 weights on every lane, so the softmax
// denominator accumulates completely per-lane (NO final reduction).
// Streaming softmax with fixed reference (sim <= 0 always; d ~ 36+/-5 so
// exp(-d) is far above fp32 underflow); final 1/sum rescale == reference.
__global__ __launch_bounds__(256, 4)
void match_attn_kernel(const float* __restrict__ moff,   // [B,N,h,2]
                       const float* __restrict__ qp,     // [B,N,C]
                       const float* __restrict__ kp,     // [B,N,C]
                       const float* __restrict__ vp,     // [B,N,C]
                       float* __restrict__ out,          // [B,N,C]
                       float* __restrict__ attn_out)     // [B,N,h,K]
{
    const int warpGlobal = (blockIdx.x * blockDim.x + threadIdx.x) >> 5;
    const int lane = threadIdx.x & 31;
    const int lig  = lane & 7;    // lane within 8-lane head group
    const int grp  = lane >> 3;   // head-in-half

    const int p = warpGlobal >> 1;               // global pixel (incl batch)
    const int g = (warpGlobal & 1) * 4 + grp;    // head id

    const int n    = p & (NPIX - 1);
    const int base = p - n;                      // b*N
    const int y    = n / WW;
    const int x    = n & (WW - 1);

    // rounded per-head window center (rintf == jnp.round, half-to-even)
    const float2 off2 = *(const float2*)&moff[(size_t)(p * NHD + g) * 2];
    const int cy = y + (int)rintf(off2.x);
    const int cx = x + (int)rintf(off2.y);

    const int chBase = g * CH + lig * 4;

    // clamped row/col element-offsets; chBase folded into the row term
    int pyW[7], pxc[7];
#pragma unroll
    for (int i = 0; i < 7; i++) {
        const int py = min(max(cy + i - RR, 0), HH - 1);
        const int px = min(max(cx + i - RR, 0), WW - 1);
        pyW[i] = (base + py * WW) * CC + chBase;
        pxc[i] = px * CC;
    }

    const float4 q4 = *(const float4*)(qp + (size_t)p * CC + chBase);

    const bool b0 = (lig & 1) != 0;
    const bool b1 = (lig & 2) != 0;
    const bool b2 = (lig & 4) != 0;
    const int  gbase = lane & 24;   // first lane of this head group

    float* aout = attn_out + (size_t)(p * NHD + g) * KWIN;

    float s = 0.f;
    float4 acc = make_float4(0.f, 0.f, 0.f, 0.f);

    // ---- prologue: group 0 addresses + k loads -------------------------------
    int    offs[4];
    float4 kst[4];
#pragma unroll
    for (int t = 0; t < 4; t++) {
        offs[t] = pyW[t / 7] + pxc[t % 7];       // kk = t (t<7 so row 0)
        kst[t]  = *(const float4*)(kp + offs[t]);
    }

#pragma unroll
    for (int j = 0; j < 12; j++) {
        // ---- v loads for THIS group: in flight across butterfly+broadcast ----
        float4 vst[4];
#pragma unroll
        for (int t = 0; t < 4; t++)
            vst[t] = *(const float4*)(vp + offs[t]);

        // ---- partial L1 distances from staged k ------------------------------
        float pd[4];
#pragma unroll
        for (int t = 0; t < 4; t++) {
            pd[t] = fabsf(q4.x - kst[t].x) + fabsf(q4.y - kst[t].y)
                  + fabsf(q4.z - kst[t].z) + fabsf(q4.w - kst[t].w);
        }

        // ---- prefetch NEXT group's k (full group of compute to hide it) ------
        if (j < 11) {
#pragma unroll
            for (int t = 0; t < 4; t++) {
                const int kk = (j + 1) * 4 + t;
                offs[t] = pyW[kk / 7] + pxc[kk % 7];
                kst[t]  = *(const float4*)(kp + offs[t]);
            }
        }

        // ---- 3-round butterfly: lanes {t, t+4} end with full d of slot 4j+t --
        float r2[2];
#pragma unroll
        for (int t = 0; t < 2; t++) {
            const float keep = b0 ? pd[2 * t + 1] : pd[2 * t];
            const float send = b0 ? pd[2 * t]     : pd[2 * t + 1];
            r2[t] = keep + __shfl_xor_sync(0xffffffffu, send, 1);
        }
        const float keep1 = b1 ? r2[1] : r2[0];
        const float send1 = b1 ? r2[0] : r2[1];
        const float dpart = keep1 + __shfl_xor_sync(0xffffffffu, send1, 2);
        const float d = dpart + __shfl_xor_sync(0xffffffffu, dpart, 4);

        const float w = __expf(-d);              // slot (4j + (lig&3)) weight
        if (lig < 4) aout[j * 4 + lig] = w;      // stash unnormalized

        // ---- broadcast all 4 weights to every lane of the group --------------
        float wt[4];
#pragma unroll
        for (int t = 0; t < 4; t++)
            wt[t] = __shfl_sync(0xffffffffu, w, gbase | t);
        s += (wt[0] + wt[1]) + (wt[2] + wt[3]);  // full sum per-lane, no reduce

        // ---- v accumulation ---------------------------------------------------
#pragma unroll
        for (int t = 0; t < 4; t++) {
            acc.x = fmaf(wt[t], vst[t].x, acc.x);
            acc.y = fmaf(wt[t], vst[t].y, acc.y);
            acc.z = fmaf(wt[t], vst[t].z, acc.z);
            acc.w = fmaf(wt[t], vst[t].w, acc.w);
        }
    }

    // ---- remainder slot 48 (row 6, col 6) ------------------------------------
    float w48;
    {
        const int off48 = pyW[6] + pxc[6];
        const float4 k4 = *(const float4*)(kp + off48);
        const float4 v4 = *(const float4*)(vp + off48);
        float d = fabsf(q4.x - k4.x) + fabsf(q4.y - k4.y)
                + fabsf(q4.z - k4.z) + fabsf(q4.w - k4.w);
        d += __shfl_xor_sync(0xffffffffu, d, 1);
        d += __shfl_xor_sync(0xffffffffu, d, 2);
        d += __shfl_xor_sync(0xffffffffu, d, 4);
        w48 = __expf(-d);                        // full weight on all 8 lanes
        s += w48;
        acc.x = fmaf(w48, v4.x, acc.x);
        acc.y = fmaf(w48, v4.y, acc.y);
        acc.z = fmaf(w48, v4.z, acc.z);
        acc.w = fmaf(w48, v4.w, acc.w);
    }

    const float inv = 1.f / s;                   // s already head-complete

    // rescale stashed weights (same thread wrote them -> ordered, L1-resident)
    if (lig < 4) {
#pragma unroll
        for (int j = 0; j < 12; j++) aout[j * 4 + lig] *= inv;
    }
    if (lig == 0) aout[48] = w48 * inv;

    acc.x *= inv; acc.y *= inv; acc.z *= inv; acc.w *= inv;
    *(float4*)(out + (size_t)p * CC + chBase) = acc;
}

extern "C" void kernel_launch(void* const* d_in, const int* in_sizes, int n_in,
                              void* d_out, int out_size) {
    const float* moff = (const float*)d_in[0];   // [B,N,h,2]
    const float* q    = (const float*)d_in[1];   // [B,N,C]
    const float* k    = (const float*)d_in[2];
    const float* v    = (const float*)d_in[3];

    float* out = (float*)d_out;                  // output [B,N,C] first...
    const int qElems = in_sizes[1];              // B*N*C
    float* attn_out = out + qElems;              // ...then attn_out [B,N,h,K]

    const int items = in_sizes[0] / 2;           // B*N*h
    const int totalWarps = items / 4;            // 4 heads per warp
    const int threads = 256;
    const int blocks = (totalWarps * 32) / threads;   // 2048

    match_attn_kernel<<<blocks, threads>>>(moff, q, k, v, out, attn_out);
}